// round 1
// baseline (speedup 1.0000x reference)
#include <cuda_runtime.h>
#include <math.h>

#define T_FRAMES 8
#define C_DIM    256
#define HW       4096
#define EPS      1e-8f
#define INV_TEMP (1.0f/0.07f)

// ---------------- device scratch (static, no allocs) ----------------
__device__ int   g_fg_idx[T_FRAMES][HW];
__device__ int   g_bg_idx[T_FRAMES][HW];
__device__ int   g_nfg[T_FRAMES];
__device__ int   g_nbg[T_FRAMES];
__device__ float g_inv[T_FRAMES][HW];
__device__ float g_fgF[T_FRAMES][C_DIM][HW];   // K-major compacted normalized fg features
__device__ float g_bgF[T_FRAMES][C_DIM][HW];   // K-major compacted normalized bg features
__device__ float g_neg[T_FRAMES][HW];
__device__ float g_frame[T_FRAMES];
__device__ float g_validf[T_FRAMES];

// ---------------- K1: labels + fg/bg compaction ----------------
__global__ void k_labels(const float* __restrict__ cur,
                         const float* __restrict__ hist,
                         float* __restrict__ out)
{
    int t = blockIdx.x, tid = threadIdx.x;
    if (tid == 0) { g_nfg[t] = 0; g_nbg[t] = 0; }
    __shared__ int s1[256], s2[256], s3[256];
    const float* cp = cur  + t * HW;
    const float* hp = hist + t * HW;
    int c1 = 0, c2 = 0, c3 = 0;
    for (int n = tid; n < HW; n += 256) {
        int cb = cp[n] > 0.5f;
        int hb = hp[n] > 0.5f;
        c1 += cb & hb; c2 += cb; c3 += hb;
    }
    s1[tid] = c1; s2[tid] = c2; s3[tid] = c3;
    __syncthreads();
    for (int off = 128; off > 0; off >>= 1) {
        if (tid < off) { s1[tid] += s1[tid+off]; s2[tid] += s2[tid+off]; s3[tid] += s3[tid+off]; }
        __syncthreads();
    }
    __shared__ int s_use;
    if (tid == 0) {
        float e1 = (float)s1[0];
        float e2 = (float)s2[0] + (float)s3[0];
        float m1 = (2.0f * e1 + EPS) / (e2 + EPS);
        float m2 = (e1 + EPS) / (e2 - e1 + EPS);
        float dev = 1.0f - (m1 + m2) * 0.5f;
        s_use = (dev <= 0.0f) ? 1 : 0;
    }
    __syncthreads();
    int use_curr = s_use;
    for (int n = tid; n < HW; n += 256) {
        float l = use_curr ? cp[n] : hp[n];
        out[t * HW + n] = l;
        if (l > 0.5f) { int p = atomicAdd(&g_nfg[t], 1); g_fg_idx[t][p] = n; }
        else          { int p = atomicAdd(&g_nbg[t], 1); g_bg_idx[t][p] = n; }
    }
}

// ---------------- K2: per-pixel inverse L2 norm ----------------
__global__ void k_norm(const float* __restrict__ feat)
{
    int p = blockIdx.x * 256 + threadIdx.x;   // 0..T*HW-1
    int t = p >> 12;
    int n = p & (HW - 1);
    const float* f = feat + (size_t)t * C_DIM * HW + n;
    float ss = 0.0f;
    #pragma unroll 8
    for (int c = 0; c < C_DIM; c++) {
        float v = f[(size_t)c * HW];
        ss = fmaf(v, v, ss);
    }
    g_inv[t][n] = 1.0f / fmaxf(sqrtf(ss), 1e-12f);
}

// ---------------- K3: gather compacted normalized features (K-major) ----------------
__global__ void k_gather(const float* __restrict__ feat)
{
    int c = blockIdx.x, t = blockIdx.y, which = blockIdx.z;
    int cnt            = which ? g_nbg[t]        : g_nfg[t];
    const int* idx     = which ? g_bg_idx[t]     : g_fg_idx[t];
    float* dst         = which ? &g_bgF[t][c][0] : &g_fgF[t][c][0];
    const float* src   = feat + ((size_t)t * C_DIM + c) * HW;
    for (int i = threadIdx.x; i < cnt; i += 256) {
        int n = idx[i];
        dst[i] = src[n] * g_inv[t][n];
    }
}

// ---------------- K4: zero neg accumulators ----------------
__global__ void k_zero()
{
    int p = blockIdx.x * 256 + threadIdx.x;
    ((float*)g_neg)[p] = 0.0f;
}

// ---------------- K5: tiled GEMM (64x64x256) + fused exp + row-sum ----------------
__global__ __launch_bounds__(256) void k_gemm()
{
    int t = blockIdx.z;
    int nfg = g_nfg[t], nbg = g_nbg[t];
    int i0 = blockIdx.y * 64;   // fg rows
    int j0 = blockIdx.x * 64;   // bg cols
    if (i0 >= nfg || j0 >= nbg) return;

    __shared__ __align__(16) float As[16][64];
    __shared__ __align__(16) float Bs[16][64];

    const float* A = &g_fgF[t][0][0];
    const float* B = &g_bgF[t][0][0];

    int tid = threadIdx.x;
    int tx = tid & 15;          // col group (4 cols)
    int ty = tid >> 4;          // row group (4 rows)
    int lc = tid >> 6;          // 0..3 (staging: c offset)
    int li = tid & 63;          // 0..63 (staging: element)

    float acc[4][4] = {};

    for (int k0 = 0; k0 < C_DIM; k0 += 16) {
        __syncthreads();
        #pragma unroll
        for (int r = 0; r < 4; r++) {
            int c = k0 + lc + r * 4;
            As[lc + r * 4][li] = A[(size_t)c * HW + i0 + li];
            Bs[lc + r * 4][li] = B[(size_t)c * HW + j0 + li];
        }
        __syncthreads();
        #pragma unroll
        for (int kk = 0; kk < 16; kk++) {
            float4 a = reinterpret_cast<const float4*>(&As[kk][0])[ty];
            float4 b = reinterpret_cast<const float4*>(&Bs[kk][0])[tx];
            acc[0][0] = fmaf(a.x, b.x, acc[0][0]); acc[0][1] = fmaf(a.x, b.y, acc[0][1]);
            acc[0][2] = fmaf(a.x, b.z, acc[0][2]); acc[0][3] = fmaf(a.x, b.w, acc[0][3]);
            acc[1][0] = fmaf(a.y, b.x, acc[1][0]); acc[1][1] = fmaf(a.y, b.y, acc[1][1]);
            acc[1][2] = fmaf(a.y, b.z, acc[1][2]); acc[1][3] = fmaf(a.y, b.w, acc[1][3]);
            acc[2][0] = fmaf(a.z, b.x, acc[2][0]); acc[2][1] = fmaf(a.z, b.y, acc[2][1]);
            acc[2][2] = fmaf(a.z, b.z, acc[2][2]); acc[2][3] = fmaf(a.z, b.w, acc[2][3]);
            acc[3][0] = fmaf(a.w, b.x, acc[3][0]); acc[3][1] = fmaf(a.w, b.y, acc[3][1]);
            acc[3][2] = fmaf(a.w, b.z, acc[3][2]); acc[3][3] = fmaf(a.w, b.w, acc[3][3]);
        }
    }

    // epilogue: exp + masked row sums, reduce across the 16 lanes sharing a row
    #pragma unroll
    for (int r = 0; r < 4; r++) {
        float s = 0.0f;
        #pragma unroll
        for (int c = 0; c < 4; c++) {
            int j = j0 + tx * 4 + c;
            if (j < nbg) s += __expf(acc[r][c] * INV_TEMP);
        }
        #pragma unroll
        for (int off = 8; off > 0; off >>= 1)
            s += __shfl_xor_sync(0xffffffffu, s, off);
        if (tx == 0) {
            int i = i0 + ty * 4 + r;
            if (i < nfg) atomicAdd(&g_neg[t][i], s);
        }
    }
}

// ---------------- K6: per-frame loss ----------------
__global__ void k_frame()
{
    int t = blockIdx.x, tid = threadIdx.x;
    int nfg = g_nfg[t], nbg = g_nbg[t];
    const float POS_INV = expf(-INV_TEMP);   // 1/pos, pos = exp(1/TEMP)
    float local = 0.0f;
    for (int i = tid; i < nfg; i += 256)
        local += log1pf((g_neg[t][i] + EPS) * POS_INV);
    __shared__ float sh[256];
    sh[tid] = local;
    __syncthreads();
    for (int off = 128; off > 0; off >>= 1) {
        if (tid < off) sh[tid] += sh[tid + off];
        __syncthreads();
    }
    if (tid == 0) {
        float fl = sh[0] / fmaxf((float)nfg, 1.0f);
        int valid = (nfg > 0 && nbg > 0) ? 1 : 0;
        g_frame[t]  = valid ? fl : 0.0f;
        g_validf[t] = (float)valid;
    }
}

// ---------------- K7: final reduction ----------------
__global__ void k_final(float* __restrict__ out, int loss_pos)
{
    if (threadIdx.x == 0) {
        float s = 0.0f, nv = 0.0f;
        for (int t = 0; t < T_FRAMES; t++) { s += g_frame[t]; nv += g_validf[t]; }
        out[loss_pos] = (nv > 0.0f) ? (s / fmaxf(nv, 1.0f)) : 0.0f;
    }
}

// ---------------- launch ----------------
extern "C" void kernel_launch(void* const* d_in, const int* in_sizes, int n_in,
                              void* d_out, int out_size)
{
    const float* cur  = (const float*)d_in[0];
    const float* hist = (const float*)d_in[1];
    const float* feat = (const float*)d_in[2];
    float* out = (float*)d_out;

    k_labels<<<T_FRAMES, 256>>>(cur, hist, out);
    k_norm<<<(T_FRAMES * HW) / 256, 256>>>(feat);
    k_gather<<<dim3(C_DIM, T_FRAMES, 2), 256>>>(feat);
    k_zero<<<(T_FRAMES * HW) / 256, 256>>>();
    k_gemm<<<dim3(HW / 64, HW / 64, T_FRAMES), 256>>>();
    k_frame<<<T_FRAMES, 256>>>();
    k_final<<<1, 32>>>(out, out_size - 1);
}

// round 4
// speedup vs baseline: 3.8664x; 3.8664x over previous
#include <cuda_runtime.h>
#include <cuda_bf16.h>
#include <stdint.h>
#include <math.h>

#define T_FRAMES 8
#define C_DIM    256
#define HW       4096
#define EPS      1e-8f
#define INV_TEMP (1.0f/0.07f)

// ---------------- device scratch (static, zero-init at load) ----------------
__device__ int   g_nfg[T_FRAMES];
__device__ int   g_nbg[T_FRAMES];
__device__ int   g_pos[T_FRAMES][HW];            // fg: p, bg: ~p
__device__ float g_inv[T_FRAMES][HW];
__device__ __nv_bfloat16 g_fgH[T_FRAMES][HW][C_DIM];  // row-major compacted normalized fg
__device__ __nv_bfloat16 g_bgH[T_FRAMES][HW][C_DIM];  // row-major compacted normalized bg
__device__ float g_neg[T_FRAMES][HW];
__device__ float g_frame[T_FRAMES];
__device__ float g_validf[T_FRAMES];

// ---------------- K1: labels + fg/bg position assignment ----------------
__global__ void k_labels(const float* __restrict__ cur,
                         const float* __restrict__ hist,
                         float* __restrict__ out)
{
    int t = blockIdx.x, tid = threadIdx.x;
    if (tid == 0) { g_nfg[t] = 0; g_nbg[t] = 0; }
    __shared__ int s1[256], s2[256], s3[256];
    const float* cp = cur  + t * HW;
    const float* hp = hist + t * HW;
    int c1 = 0, c2 = 0, c3 = 0;
    for (int n = tid; n < HW; n += 256) {
        int cb = cp[n] > 0.5f;
        int hb = hp[n] > 0.5f;
        c1 += cb & hb; c2 += cb; c3 += hb;
    }
    s1[tid] = c1; s2[tid] = c2; s3[tid] = c3;
    __syncthreads();
    for (int off = 128; off > 0; off >>= 1) {
        if (tid < off) { s1[tid] += s1[tid+off]; s2[tid] += s2[tid+off]; s3[tid] += s3[tid+off]; }
        __syncthreads();
    }
    __shared__ int s_use;
    if (tid == 0) {
        float e1 = (float)s1[0];
        float e2 = (float)s2[0] + (float)s3[0];
        float m1 = (2.0f * e1 + EPS) / (e2 + EPS);
        float m2 = (e1 + EPS) / (e2 - e1 + EPS);
        float dev = 1.0f - (m1 + m2) * 0.5f;
        s_use = (dev <= 0.0f) ? 1 : 0;
    }
    __syncthreads();
    int use_curr = s_use;
    for (int n = tid; n < HW; n += 256) {
        float l = use_curr ? cp[n] : hp[n];
        out[t * HW + n] = l;
        if (l > 0.5f) { int p = atomicAdd(&g_nfg[t], 1); g_pos[t][n] = p; }
        else          { int p = atomicAdd(&g_nbg[t], 1); g_pos[t][n] = ~p; }
    }
}

// ---------------- K2: per-pixel inverse L2 norm ----------------
__global__ void k_norm(const float* __restrict__ feat)
{
    int p = blockIdx.x * 256 + threadIdx.x;
    int t = p >> 12;
    int n = p & (HW - 1);
    const float* f = feat + (size_t)t * C_DIM * HW + n;
    float ss = 0.0f;
    #pragma unroll 8
    for (int c = 0; c < C_DIM; c++) {
        float v = f[(size_t)c * HW];
        ss = fmaf(v, v, ss);
    }
    g_inv[t][n] = 1.0f / fmaxf(sqrtf(ss), 1e-12f);
}

// ---------------- K3: transpose-gather normalized bf16 features ----------------
// grid (HW/32, C/32, T), block (32, 8)
__global__ void k_gather(const float* __restrict__ feat)
{
    __shared__ __nv_bfloat16 sm[32][33];
    int n0 = blockIdx.x * 32, c0 = blockIdx.y * 32, t = blockIdx.z;
    int x = threadIdx.x, y = threadIdx.y;
    int n = n0 + x;
    float inv = g_inv[t][n];
    const float* src = feat + ((size_t)t * C_DIM + c0) * HW + n;
    #pragma unroll
    for (int cs = 0; cs < 4; cs++) {
        int cl = y + cs * 8;
        sm[cl][x] = __float2bfloat16(src[(size_t)cl * HW] * inv);
    }
    __syncthreads();
    int w = y * 32 + x;
    int nl = w >> 3, part = w & 7;
    int pp = g_pos[t][n0 + nl];
    __nv_bfloat16* dst = (pp >= 0) ? &g_fgH[t][pp][0] : &g_bgH[t][~pp][0];
    __nv_bfloat16 v[4];
    #pragma unroll
    for (int i2 = 0; i2 < 4; i2++) v[i2] = sm[part * 4 + i2][nl];
    *(uint2*)&dst[c0 + part * 4] = *(uint2*)v;
}

// ---------------- K4: zero neg accumulators ----------------
__global__ void k_zero()
{
    int p = blockIdx.x * 256 + threadIdx.x;
    ((float*)g_neg)[p] = 0.0f;
}

// ---------------- K5: bf16 tensor-core GEMM (128x128x256) + fused exp + row-sum ----------------
__global__ __launch_bounds__(256) void k_gemm()
{
    int t = blockIdx.z;
    int nfg = g_nfg[t], nbg = g_nbg[t];
    int i0 = blockIdx.y * 128;
    int j0 = blockIdx.x * 128;
    if (i0 >= nfg || j0 >= nbg) return;

    __shared__ __align__(16) __nv_bfloat16 As[128][40];
    __shared__ __align__(16) __nv_bfloat16 Bs[128][40];

    const __nv_bfloat16* A = &g_fgH[t][0][0];
    const __nv_bfloat16* B = &g_bgH[t][0][0];

    int tid = threadIdx.x;
    int lane = tid & 31, wid = tid >> 5;
    int wrow = wid >> 2, wcol = wid & 3;     // 2 (m) x 4 (n) warps
    int srow = tid >> 2;
    int scol = (tid & 3) * 8;

    float acc[4][4][4] = {};

    for (int k0 = 0; k0 < C_DIM; k0 += 32) {
        __syncthreads();
        #pragma unroll
        for (int h = 0; h < 2; h++) {
            int r = srow + h * 64;
            *(uint4*)&As[r][scol] = *(const uint4*)&A[(size_t)(i0 + r) * C_DIM + k0 + scol];
            *(uint4*)&Bs[r][scol] = *(const uint4*)&B[(size_t)(j0 + r) * C_DIM + k0 + scol];
        }
        __syncthreads();
        #pragma unroll
        for (int ks = 0; ks < 32; ks += 16) {
            uint32_t bfr[4][2];
            #pragma unroll
            for (int nt = 0; nt < 4; nt++) {
                int nrow = wcol * 32 + nt * 8 + (lane & 7);
                int ncol = ks + ((lane >> 3) & 1) * 8;
                uint32_t addr = (uint32_t)__cvta_generic_to_shared(&Bs[nrow][ncol]);
                asm volatile("ldmatrix.sync.aligned.m8n8.x2.shared.b16 {%0,%1}, [%2];"
                    : "=r"(bfr[nt][0]), "=r"(bfr[nt][1]) : "r"(addr));
            }
            #pragma unroll
            for (int mt = 0; mt < 4; mt++) {
                int mrow = wrow * 64 + mt * 16 + (lane & 7) + ((lane >> 3) & 1) * 8;
                int mcol = ks + (lane >> 4) * 8;
                uint32_t addr = (uint32_t)__cvta_generic_to_shared(&As[mrow][mcol]);
                uint32_t af[4];
                asm volatile("ldmatrix.sync.aligned.m8n8.x4.shared.b16 {%0,%1,%2,%3}, [%4];"
                    : "=r"(af[0]), "=r"(af[1]), "=r"(af[2]), "=r"(af[3]) : "r"(addr));
                #pragma unroll
                for (int nt = 0; nt < 4; nt++) {
                    asm volatile(
                        "mma.sync.aligned.m16n8k16.row.col.f32.bf16.bf16.f32 "
                        "{%0,%1,%2,%3}, {%4,%5,%6,%7}, {%8,%9}, {%0,%1,%2,%3};"
                        : "+f"(acc[mt][nt][0]), "+f"(acc[mt][nt][1]),
                          "+f"(acc[mt][nt][2]), "+f"(acc[mt][nt][3])
                        : "r"(af[0]), "r"(af[1]), "r"(af[2]), "r"(af[3]),
                          "r"(bfr[nt][0]), "r"(bfr[nt][1]));
                }
            }
        }
    }

    // epilogue: exp + masked row sums
    int g = lane >> 2, tg = lane & 3;
    #pragma unroll
    for (int mt = 0; mt < 4; mt++) {
        float slo = 0.0f, shi = 0.0f;
        #pragma unroll
        for (int nt = 0; nt < 4; nt++) {
            int jb = j0 + wcol * 32 + nt * 8 + 2 * tg;
            if (jb < nbg)     { slo += __expf(acc[mt][nt][0] * INV_TEMP);
                                shi += __expf(acc[mt][nt][2] * INV_TEMP); }
            if (jb + 1 < nbg) { slo += __expf(acc[mt][nt][1] * INV_TEMP);
                                shi += __expf(acc[mt][nt][3] * INV_TEMP); }
        }
        slo += __shfl_xor_sync(0xffffffffu, slo, 1);
        slo += __shfl_xor_sync(0xffffffffu, slo, 2);
        shi += __shfl_xor_sync(0xffffffffu, shi, 1);
        shi += __shfl_xor_sync(0xffffffffu, shi, 2);
        if (tg == 0) {
            int i = i0 + wrow * 64 + mt * 16 + g;
            if (i < nfg)     atomicAdd(&g_neg[t][i], slo);
            if (i + 8 < nfg) atomicAdd(&g_neg[t][i + 8], shi);
        }
    }
}

// ---------------- K6: per-frame loss ----------------
__global__ void k_frame()
{
    int t = blockIdx.x, tid = threadIdx.x;
    int nfg = g_nfg[t], nbg = g_nbg[t];
    const float POS_INV = expf(-INV_TEMP);
    float local = 0.0f;
    for (int i = tid; i < nfg; i += 256)
        local += log1pf((g_neg[t][i] + EPS) * POS_INV);
    __shared__ float sh[256];
    sh[tid] = local;
    __syncthreads();
    for (int off = 128; off > 0; off >>= 1) {
        if (tid < off) sh[tid] += sh[tid + off];
        __syncthreads();
    }
    if (tid == 0) {
        float fl = sh[0] / fmaxf((float)nfg, 1.0f);
        int valid = (nfg > 0 && nbg > 0) ? 1 : 0;
        g_frame[t]  = valid ? fl : 0.0f;
        g_validf[t] = (float)valid;
    }
}

// ---------------- K7: final reduction ----------------
__global__ void k_final(float* __restrict__ out, int loss_pos)
{
    if (threadIdx.x == 0) {
        float s = 0.0f, nv = 0.0f;
        for (int t = 0; t < T_FRAMES; t++) { s += g_frame[t]; nv += g_validf[t]; }
        out[loss_pos] = (nv > 0.0f) ? (s / fmaxf(nv, 1.0f)) : 0.0f;
    }
}

// ---------------- launch ----------------
extern "C" void kernel_launch(void* const* d_in, const int* in_sizes, int n_in,
                              void* d_out, int out_size)
{
    const float* cur  = (const float*)d_in[0];
    const float* hist = (const float*)d_in[1];
    const float* feat = (const float*)d_in[2];
    float* out = (float*)d_out;

    k_labels<<<T_FRAMES, 256>>>(cur, hist, out);
    k_norm<<<(T_FRAMES * HW) / 256, 256>>>(feat);
    k_gather<<<dim3(HW / 32, C_DIM / 32, T_FRAMES), dim3(32, 8)>>>(feat);
    k_zero<<<(T_FRAMES * HW) / 256, 256>>>();
    k_gemm<<<dim3(HW / 128, HW / 128, T_FRAMES), 256>>>();
    k_frame<<<T_FRAMES, 256>>>();
    k_final<<<1, 32>>>(out, out_size - 1);
}

// round 5
// speedup vs baseline: 4.2349x; 1.0953x over previous
#include <cuda_runtime.h>
#include <cuda_bf16.h>
#include <stdint.h>
#include <math.h>

#define T_FRAMES 8
#define C_DIM    256
#define HW       4096
#define EPS      1e-8f
#define INV_TEMP (1.0f/0.07f)

// ---------------- device scratch (static, zero-init at load) ----------------
__device__ int   g_nfg[T_FRAMES];
__device__ int   g_nbg[T_FRAMES];
__device__ int   g_pos[T_FRAMES][HW];            // fg: p, bg: ~p
__device__ __nv_bfloat16 g_fgH[T_FRAMES][HW][C_DIM];  // row-major compacted normalized fg
__device__ __nv_bfloat16 g_bgH[T_FRAMES][HW][C_DIM];  // row-major compacted normalized bg
__device__ float g_neg[T_FRAMES][HW];
__device__ float g_frame[T_FRAMES];
__device__ float g_validf[T_FRAMES];

// ---------------- K1: labels + fg/bg position assignment + neg zeroing ----------------
__global__ void k_labels(const float* __restrict__ cur,
                         const float* __restrict__ hist,
                         float* __restrict__ out)
{
    int t = blockIdx.x, tid = threadIdx.x;
    if (tid == 0) { g_nfg[t] = 0; g_nbg[t] = 0; }
    __shared__ int s1[256], s2[256], s3[256];
    const float* cp = cur  + t * HW;
    const float* hp = hist + t * HW;
    int c1 = 0, c2 = 0, c3 = 0;
    for (int n = tid; n < HW; n += 256) {
        int cb = cp[n] > 0.5f;
        int hb = hp[n] > 0.5f;
        c1 += cb & hb; c2 += cb; c3 += hb;
    }
    s1[tid] = c1; s2[tid] = c2; s3[tid] = c3;
    __syncthreads();
    for (int off = 128; off > 0; off >>= 1) {
        if (tid < off) { s1[tid] += s1[tid+off]; s2[tid] += s2[tid+off]; s3[tid] += s3[tid+off]; }
        __syncthreads();
    }
    __shared__ int s_use;
    if (tid == 0) {
        float e1 = (float)s1[0];
        float e2 = (float)s2[0] + (float)s3[0];
        float m1 = (2.0f * e1 + EPS) / (e2 + EPS);
        float m2 = (e1 + EPS) / (e2 - e1 + EPS);
        float dev = 1.0f - (m1 + m2) * 0.5f;
        s_use = (dev <= 0.0f) ? 1 : 0;
    }
    __syncthreads();
    int use_curr = s_use;
    for (int n = tid; n < HW; n += 256) {
        float l = use_curr ? cp[n] : hp[n];
        out[t * HW + n] = l;
        g_neg[t][n] = 0.0f;
        if (l > 0.5f) { int p = atomicAdd(&g_nfg[t], 1); g_pos[t][n] = p; }
        else          { int p = atomicAdd(&g_nbg[t], 1); g_pos[t][n] = ~p; }
    }
}

// ---------------- K2: fused norm + transpose-gather of normalized bf16 features ----------------
// grid (HW/32, T), block (32, 8)
__global__ __launch_bounds__(256) void k_normgather(const float* __restrict__ feat)
{
    __shared__ float sf[32][260];       // [pixel][channel], 260 pad: 16B-aligned rows
    __shared__ float ssp[8][32];
    __shared__ float sinv[32];
    int n0 = blockIdx.x * 32, t = blockIdx.y;
    int x = threadIdx.x, y = threadIdx.y;

    const float* base = feat + (size_t)t * C_DIM * HW + n0 + x;
    float ss = 0.0f;
    #pragma unroll
    for (int cs = 0; cs < 32; cs++) {
        int c = y + cs * 8;
        float v = base[(size_t)c * HW];
        sf[x][c] = v;
        ss = fmaf(v, v, ss);
    }
    ssp[y][x] = ss;
    __syncthreads();
    if (y == 0) {
        float s = 0.0f;
        #pragma unroll
        for (int i = 0; i < 8; i++) s += ssp[i][x];
        sinv[x] = 1.0f / fmaxf(sqrtf(s), 1e-12f);
    }
    __syncthreads();

    int w = y * 32 + x;
    int nl = w >> 3, part = w & 7;      // pixel, 1/8 of its row
    int pp = g_pos[t][n0 + nl];
    __nv_bfloat16* dst = (pp >= 0) ? &g_fgH[t][pp][0] : &g_bgH[t][~pp][0];
    float inv = sinv[nl];
    #pragma unroll
    for (int q = 0; q < 4; q++) {       // 4 x 16B stores = 32 channels
        int c = part * 32 + q * 8;
        float4 v0 = *(const float4*)&sf[nl][c];
        float4 v1 = *(const float4*)&sf[nl][c + 4];
        __nv_bfloat16 v[8];
        v[0] = __float2bfloat16(v0.x * inv); v[1] = __float2bfloat16(v0.y * inv);
        v[2] = __float2bfloat16(v0.z * inv); v[3] = __float2bfloat16(v0.w * inv);
        v[4] = __float2bfloat16(v1.x * inv); v[5] = __float2bfloat16(v1.y * inv);
        v[6] = __float2bfloat16(v1.z * inv); v[7] = __float2bfloat16(v1.w * inv);
        *(uint4*)&dst[c] = *(uint4*)v;
    }
}

// ---------------- K3: bf16 tensor-core GEMM (128x128x256), double-buffered ----------------
__global__ __launch_bounds__(256, 2) void k_gemm()
{
    int t = blockIdx.z;
    int nfg = g_nfg[t], nbg = g_nbg[t];
    int i0 = blockIdx.y * 128;
    int j0 = blockIdx.x * 128;
    if (i0 >= nfg || j0 >= nbg) return;

    __shared__ __align__(16) __nv_bfloat16 As[2][128][40];
    __shared__ __align__(16) __nv_bfloat16 Bs[2][128][40];

    const __nv_bfloat16* A = &g_fgH[t][0][0];
    const __nv_bfloat16* B = &g_bgH[t][0][0];

    int tid = threadIdx.x;
    int lane = tid & 31, wid = tid >> 5;
    int wrow = wid >> 2, wcol = wid & 3;     // 2 (m) x 4 (n) warps
    int srow = tid >> 2;
    int scol = (tid & 3) * 8;

    float acc[4][4][4] = {};
    uint4 ra[2], rb[2];

    // prologue: chunk 0 -> buffer 0
    #pragma unroll
    for (int h = 0; h < 2; h++) {
        int r = srow + h * 64;
        ra[h] = *(const uint4*)&A[(size_t)(i0 + r) * C_DIM + scol];
        rb[h] = *(const uint4*)&B[(size_t)(j0 + r) * C_DIM + scol];
    }
    #pragma unroll
    for (int h = 0; h < 2; h++) {
        int r = srow + h * 64;
        *(uint4*)&As[0][r][scol] = ra[h];
        *(uint4*)&Bs[0][r][scol] = rb[h];
    }

    #pragma unroll
    for (int ch = 0; ch < 8; ch++) {
        __syncthreads();
        if (ch < 7) {
            int k0 = (ch + 1) * 32;
            #pragma unroll
            for (int h = 0; h < 2; h++) {
                int r = srow + h * 64;
                ra[h] = *(const uint4*)&A[(size_t)(i0 + r) * C_DIM + k0 + scol];
                rb[h] = *(const uint4*)&B[(size_t)(j0 + r) * C_DIM + k0 + scol];
            }
        }
        int buf = ch & 1;
        #pragma unroll
        for (int ks = 0; ks < 32; ks += 16) {
            uint32_t bfr[4][2];
            #pragma unroll
            for (int p = 0; p < 2; p++) {   // nt pairs {0,1}, {2,3} in one x4
                int grp = lane >> 3;
                int nrow = wcol * 32 + p * 16 + ((grp >> 1) << 3) + (lane & 7);
                int ncol = ks + ((grp & 1) << 3);
                uint32_t addr = (uint32_t)__cvta_generic_to_shared(&Bs[buf][nrow][ncol]);
                asm volatile("ldmatrix.sync.aligned.m8n8.x4.shared.b16 {%0,%1,%2,%3}, [%4];"
                    : "=r"(bfr[2*p][0]), "=r"(bfr[2*p][1]),
                      "=r"(bfr[2*p+1][0]), "=r"(bfr[2*p+1][1]) : "r"(addr));
            }
            #pragma unroll
            for (int mt = 0; mt < 4; mt++) {
                int mrow = wrow * 64 + mt * 16 + (lane & 7) + ((lane >> 3) & 1) * 8;
                int mcol = ks + (lane >> 4) * 8;
                uint32_t addr = (uint32_t)__cvta_generic_to_shared(&As[buf][mrow][mcol]);
                uint32_t af[4];
                asm volatile("ldmatrix.sync.aligned.m8n8.x4.shared.b16 {%0,%1,%2,%3}, [%4];"
                    : "=r"(af[0]), "=r"(af[1]), "=r"(af[2]), "=r"(af[3]) : "r"(addr));
                #pragma unroll
                for (int nt = 0; nt < 4; nt++) {
                    asm volatile(
                        "mma.sync.aligned.m16n8k16.row.col.f32.bf16.bf16.f32 "
                        "{%0,%1,%2,%3}, {%4,%5,%6,%7}, {%8,%9}, {%0,%1,%2,%3};"
                        : "+f"(acc[mt][nt][0]), "+f"(acc[mt][nt][1]),
                          "+f"(acc[mt][nt][2]), "+f"(acc[mt][nt][3])
                        : "r"(af[0]), "r"(af[1]), "r"(af[2]), "r"(af[3]),
                          "r"(bfr[nt][0]), "r"(bfr[nt][1]));
                }
            }
        }
        if (ch < 7) {
            int nb = (ch + 1) & 1;
            #pragma unroll
            for (int h = 0; h < 2; h++) {
                int r = srow + h * 64;
                *(uint4*)&As[nb][r][scol] = ra[h];
                *(uint4*)&Bs[nb][r][scol] = rb[h];
            }
        }
    }

    // epilogue: exp + masked row sums
    int g = lane >> 2, tg = lane & 3;
    #pragma unroll
    for (int mt = 0; mt < 4; mt++) {
        float slo = 0.0f, shi = 0.0f;
        #pragma unroll
        for (int nt = 0; nt < 4; nt++) {
            int jb = j0 + wcol * 32 + nt * 8 + 2 * tg;
            if (jb < nbg)     { slo += __expf(acc[mt][nt][0] * INV_TEMP);
                                shi += __expf(acc[mt][nt][2] * INV_TEMP); }
            if (jb + 1 < nbg) { slo += __expf(acc[mt][nt][1] * INV_TEMP);
                                shi += __expf(acc[mt][nt][3] * INV_TEMP); }
        }
        slo += __shfl_xor_sync(0xffffffffu, slo, 1);
        slo += __shfl_xor_sync(0xffffffffu, slo, 2);
        shi += __shfl_xor_sync(0xffffffffu, shi, 1);
        shi += __shfl_xor_sync(0xffffffffu, shi, 2);
        if (tg == 0) {
            int i = i0 + wrow * 64 + mt * 16 + g;
            if (i < nfg)     atomicAdd(&g_neg[t][i], slo);
            if (i + 8 < nfg) atomicAdd(&g_neg[t][i + 8], shi);
        }
    }
}

// ---------------- K4: per-frame loss ----------------
__global__ void k_frame()
{
    int t = blockIdx.x, tid = threadIdx.x;
    int nfg = g_nfg[t], nbg = g_nbg[t];
    const float POS_INV = expf(-INV_TEMP);
    float local = 0.0f;
    for (int i = tid; i < nfg; i += 256)
        local += log1pf((g_neg[t][i] + EPS) * POS_INV);
    __shared__ float sh[256];
    sh[tid] = local;
    __syncthreads();
    for (int off = 128; off > 0; off >>= 1) {
        if (tid < off) sh[tid] += sh[tid + off];
        __syncthreads();
    }
    if (tid == 0) {
        float fl = sh[0] / fmaxf((float)nfg, 1.0f);
        int valid = (nfg > 0 && nbg > 0) ? 1 : 0;
        g_frame[t]  = valid ? fl : 0.0f;
        g_validf[t] = (float)valid;
    }
}

// ---------------- K5: final reduction ----------------
__global__ void k_final(float* __restrict__ out, int loss_pos)
{
    if (threadIdx.x == 0) {
        float s = 0.0f, nv = 0.0f;
        for (int t = 0; t < T_FRAMES; t++) { s += g_frame[t]; nv += g_validf[t]; }
        out[loss_pos] = (nv > 0.0f) ? (s / fmaxf(nv, 1.0f)) : 0.0f;
    }
}

// ---------------- launch ----------------
extern "C" void kernel_launch(void* const* d_in, const int* in_sizes, int n_in,
                              void* d_out, int out_size)
{
    const float* cur  = (const float*)d_in[0];
    const float* hist = (const float*)d_in[1];
    const float* feat = (const float*)d_in[2];
    float* out = (float*)d_out;

    k_labels<<<T_FRAMES, 256>>>(cur, hist, out);
    k_normgather<<<dim3(HW / 32, T_FRAMES), dim3(32, 8)>>>(feat);
    k_gemm<<<dim3(HW / 128, HW / 128, T_FRAMES), 256>>>();
    k_frame<<<T_FRAMES, 256>>>();
    k_final<<<1, 32>>>(out, out_size - 1);
}

// round 7
// speedup vs baseline: 4.7957x; 1.1324x over previous
#include <cuda_runtime.h>
#include <cuda_bf16.h>
#include <stdint.h>
#include <math.h>

#define T_FRAMES 8
#define C_DIM    256
#define HW       4096
#define EPS      1e-8f
#define INV_TEMP (1.0f/0.07f)

// ---------------- device scratch (static, zero-init at load) ----------------
__device__ int   g_nfg[T_FRAMES];
__device__ int   g_nbg[T_FRAMES];
__device__ int   g_pos[T_FRAMES][HW];            // fg: p, bg: ~p
__device__ __nv_bfloat16 g_fgH[T_FRAMES][HW][C_DIM];  // row-major compacted normalized fg
__device__ __nv_bfloat16 g_bgH[T_FRAMES][HW][C_DIM];  // row-major compacted normalized bg
__device__ float g_neg[T_FRAMES][HW];
__device__ float g_frame[T_FRAMES];
__device__ float g_validf[T_FRAMES];

#define CP_ASYNC16(dst, src) \
    asm volatile("cp.async.cg.shared.global [%0], [%1], 16;" :: "r"(dst), "l"(src))
#define CP_COMMIT() asm volatile("cp.async.commit_group;" ::: "memory")
#define CP_WAIT1()  asm volatile("cp.async.wait_group 1;" ::: "memory")
#define CP_WAIT0()  asm volatile("cp.async.wait_group 0;" ::: "memory")

// ---------------- K1: labels + fg/bg position assignment + neg zeroing ----------------
__global__ void k_labels(const float* __restrict__ cur,
                         const float* __restrict__ hist,
                         float* __restrict__ out)
{
    int t = blockIdx.x, tid = threadIdx.x;
    if (tid == 0) { g_nfg[t] = 0; g_nbg[t] = 0; }
    __shared__ int s1[256], s2[256], s3[256];
    const float* cp = cur  + t * HW;
    const float* hp = hist + t * HW;
    int c1 = 0, c2 = 0, c3 = 0;
    for (int n = tid; n < HW; n += 256) {
        int cb = cp[n] > 0.5f;
        int hb = hp[n] > 0.5f;
        c1 += cb & hb; c2 += cb; c3 += hb;
    }
    s1[tid] = c1; s2[tid] = c2; s3[tid] = c3;
    __syncthreads();
    for (int off = 128; off > 0; off >>= 1) {
        if (tid < off) { s1[tid] += s1[tid+off]; s2[tid] += s2[tid+off]; s3[tid] += s3[tid+off]; }
        __syncthreads();
    }
    __shared__ int s_use;
    if (tid == 0) {
        float e1 = (float)s1[0];
        float e2 = (float)s2[0] + (float)s3[0];
        float m1 = (2.0f * e1 + EPS) / (e2 + EPS);
        float m2 = (e1 + EPS) / (e2 - e1 + EPS);
        float dev = 1.0f - (m1 + m2) * 0.5f;
        s_use = (dev <= 0.0f) ? 1 : 0;
    }
    __syncthreads();
    int use_curr = s_use;
    for (int n = tid; n < HW; n += 256) {
        float l = use_curr ? cp[n] : hp[n];
        out[t * HW + n] = l;
        g_neg[t][n] = 0.0f;
        if (l > 0.5f) { int p = atomicAdd(&g_nfg[t], 1); g_pos[t][n] = p; }
        else          { int p = atomicAdd(&g_nbg[t], 1); g_pos[t][n] = ~p; }
    }
}

// ---------------- K2: fused norm + transpose-gather of normalized bf16 features ----------------
// grid (HW/32, T), block (32, 8)
__global__ __launch_bounds__(256) void k_normgather(const float* __restrict__ feat)
{
    __shared__ float sf[32][260];
    __shared__ float ssp[8][32];
    __shared__ float sinv[32];
    int n0 = blockIdx.x * 32, t = blockIdx.y;
    int x = threadIdx.x, y = threadIdx.y;

    const float* base = feat + (size_t)t * C_DIM * HW + n0 + x;
    float ss = 0.0f;
    #pragma unroll
    for (int cs = 0; cs < 32; cs++) {
        int c = y + cs * 8;
        float v = base[(size_t)c * HW];
        sf[x][c] = v;
        ss = fmaf(v, v, ss);
    }
    ssp[y][x] = ss;
    __syncthreads();
    if (y == 0) {
        float s = 0.0f;
        #pragma unroll
        for (int i = 0; i < 8; i++) s += ssp[i][x];
        sinv[x] = 1.0f / fmaxf(sqrtf(s), 1e-12f);
    }
    __syncthreads();

    int w = y * 32 + x;
    int nl = w >> 3, part = w & 7;
    int pp = g_pos[t][n0 + nl];
    __nv_bfloat16* dst = (pp >= 0) ? &g_fgH[t][pp][0] : &g_bgH[t][~pp][0];
    float inv = sinv[nl];
    #pragma unroll
    for (int q = 0; q < 4; q++) {
        int c = part * 32 + q * 8;
        float4 v0 = *(const float4*)&sf[nl][c];
        float4 v1 = *(const float4*)&sf[nl][c + 4];
        __nv_bfloat16 v[8];
        v[0] = __float2bfloat16(v0.x * inv); v[1] = __float2bfloat16(v0.y * inv);
        v[2] = __float2bfloat16(v0.z * inv); v[3] = __float2bfloat16(v0.w * inv);
        v[4] = __float2bfloat16(v1.x * inv); v[5] = __float2bfloat16(v1.y * inv);
        v[6] = __float2bfloat16(v1.z * inv); v[7] = __float2bfloat16(v1.w * inv);
        *(uint4*)&dst[c] = *(uint4*)v;
    }
}

// ---------------- K3: bf16 mma.sync GEMM, 3-stage cp.async pipeline ----------------
__global__ __launch_bounds__(256, 2) void k_gemm()
{
    int t = blockIdx.z;
    int nfg = g_nfg[t], nbg = g_nbg[t];
    int i0 = blockIdx.y * 128;
    int j0 = blockIdx.x * 128;
    if (i0 >= nfg || j0 >= nbg) return;

    __shared__ __align__(16) __nv_bfloat16 As[3][128][40];
    __shared__ __align__(16) __nv_bfloat16 Bs[3][128][40];

    const __nv_bfloat16* A = &g_fgH[t][0][0];
    const __nv_bfloat16* B = &g_bgH[t][0][0];

    int tid = threadIdx.x;
    int lane = tid & 31, wid = tid >> 5;
    int wrow = wid >> 2, wcol = wid & 3;     // 2 (m) x 4 (n) warps
    int srow = tid >> 2;
    int scol = (tid & 3) * 8;

    float acc[4][4][4] = {};

    // issue loads for a K-chunk into stage s
    auto issue = [&](int ch, int s) {
        int k0 = ch * 32;
        #pragma unroll
        for (int h = 0; h < 2; h++) {
            int r = srow + h * 64;
            uint32_t da = (uint32_t)__cvta_generic_to_shared(&As[s][r][scol]);
            uint32_t db = (uint32_t)__cvta_generic_to_shared(&Bs[s][r][scol]);
            CP_ASYNC16(da, &A[(size_t)(i0 + r) * C_DIM + k0 + scol]);
            CP_ASYNC16(db, &B[(size_t)(j0 + r) * C_DIM + k0 + scol]);
        }
        CP_COMMIT();
    };

    issue(0, 0);
    issue(1, 1);

    #pragma unroll
    for (int ch = 0; ch < 8; ch++) {
        if (ch < 6) CP_WAIT1(); else CP_WAIT0();
        __syncthreads();
        if (ch + 2 < 8) issue(ch + 2, (ch + 2) % 3);

        int buf = ch % 3;
        #pragma unroll
        for (int ks = 0; ks < 32; ks += 16) {
            uint32_t bfr[4][2];
            #pragma unroll
            for (int p = 0; p < 2; p++) {
                int grp = lane >> 3;
                int nrow = wcol * 32 + p * 16 + ((grp >> 1) << 3) + (lane & 7);
                int ncol = ks + ((grp & 1) << 3);
                uint32_t addr = (uint32_t)__cvta_generic_to_shared(&Bs[buf][nrow][ncol]);
                asm volatile("ldmatrix.sync.aligned.m8n8.x4.shared.b16 {%0,%1,%2,%3}, [%4];"
                    : "=r"(bfr[2*p][0]), "=r"(bfr[2*p][1]),
                      "=r"(bfr[2*p+1][0]), "=r"(bfr[2*p+1][1]) : "r"(addr));
            }
            #pragma unroll
            for (int mt = 0; mt < 4; mt++) {
                int mrow = wrow * 64 + mt * 16 + (lane & 7) + ((lane >> 3) & 1) * 8;
                int mcol = ks + (lane >> 4) * 8;
                uint32_t addr = (uint32_t)__cvta_generic_to_shared(&As[buf][mrow][mcol]);
                uint32_t af[4];
                asm volatile("ldmatrix.sync.aligned.m8n8.x4.shared.b16 {%0,%1,%2,%3}, [%4];"
                    : "=r"(af[0]), "=r"(af[1]), "=r"(af[2]), "=r"(af[3]) : "r"(addr));
                #pragma unroll
                for (int nt = 0; nt < 4; nt++) {
                    asm volatile(
                        "mma.sync.aligned.m16n8k16.row.col.f32.bf16.bf16.f32 "
                        "{%0,%1,%2,%3}, {%4,%5,%6,%7}, {%8,%9}, {%0,%1,%2,%3};"
                        : "+f"(acc[mt][nt][0]), "+f"(acc[mt][nt][1]),
                          "+f"(acc[mt][nt][2]), "+f"(acc[mt][nt][3])
                        : "r"(af[0]), "r"(af[1]), "r"(af[2]), "r"(af[3]),
                          "r"(bfr[nt][0]), "r"(bfr[nt][1]));
                }
            }
        }
        __syncthreads();
    }

    // epilogue: exp + masked row sums
    int g = lane >> 2, tg = lane & 3;
    #pragma unroll
    for (int mt = 0; mt < 4; mt++) {
        float slo = 0.0f, shi = 0.0f;
        #pragma unroll
        for (int nt = 0; nt < 4; nt++) {
            int jb = j0 + wcol * 32 + nt * 8 + 2 * tg;
            if (jb < nbg)     { slo += __expf(acc[mt][nt][0] * INV_TEMP);
                                shi += __expf(acc[mt][nt][2] * INV_TEMP); }
            if (jb + 1 < nbg) { slo += __expf(acc[mt][nt][1] * INV_TEMP);
                                shi += __expf(acc[mt][nt][3] * INV_TEMP); }
        }
        slo += __shfl_xor_sync(0xffffffffu, slo, 1);
        slo += __shfl_xor_sync(0xffffffffu, slo, 2);
        shi += __shfl_xor_sync(0xffffffffu, shi, 1);
        shi += __shfl_xor_sync(0xffffffffu, shi, 2);
        if (tg == 0) {
            int i = i0 + wrow * 64 + mt * 16 + g;
            if (i < nfg)     atomicAdd(&g_neg[t][i], slo);
            if (i + 8 < nfg) atomicAdd(&g_neg[t][i + 8], shi);
        }
    }
}

// ---------------- K4: per-frame loss ----------------
__global__ void k_frame()
{
    int t = blockIdx.x, tid = threadIdx.x;
    int nfg = g_nfg[t], nbg = g_nbg[t];
    const float POS_INV = expf(-INV_TEMP);
    float local = 0.0f;
    for (int i = tid; i < nfg; i += 256)
        local += log1pf((g_neg[t][i] + EPS) * POS_INV);
    __shared__ float sh[256];
    sh[tid] = local;
    __syncthreads();
    for (int off = 128; off > 0; off >>= 1) {
        if (tid < off) sh[tid] += sh[tid + off];
        __syncthreads();
    }
    if (tid == 0) {
        float fl = sh[0] / fmaxf((float)nfg, 1.0f);
        int valid = (nfg > 0 && nbg > 0) ? 1 : 0;
        g_frame[t]  = valid ? fl : 0.0f;
        g_validf[t] = (float)valid;
    }
}

// ---------------- K5: final reduction ----------------
__global__ void k_final(float* __restrict__ out, int loss_pos)
{
    if (threadIdx.x == 0) {
        float s = 0.0f, nv = 0.0f;
        for (int t = 0; t < T_FRAMES; t++) { s += g_frame[t]; nv += g_validf[t]; }
        out[loss_pos] = (nv > 0.0f) ? (s / fmaxf(nv, 1.0f)) : 0.0f;
    }
}

// ---------------- launch ----------------
extern "C" void kernel_launch(void* const* d_in, const int* in_sizes, int n_in,
                              void* d_out, int out_size)
{
    const float* cur  = (const float*)d_in[0];
    const float* hist = (const float*)d_in[1];
    const float* feat = (const float*)d_in[2];
    float* out = (float*)d_out;

    k_labels<<<T_FRAMES, 256>>>(cur, hist, out);
    k_normgather<<<dim3(HW / 32, T_FRAMES), dim3(32, 8)>>>(feat);
    k_gemm<<<dim3(HW / 128, HW / 128, T_FRAMES), 256>>>();
    k_frame<<<T_FRAMES, 256>>>();
    k_final<<<1, 32>>>(out, out_size - 1);
}